// round 8
// baseline (speedup 1.0000x reference)
#include <cuda_runtime.h>

// ConsensusAttention: levels [B=8, N=1024, L=6, D=128] fp32.
// Local attention: each token attends to <=13 neighbors (dy^2+dx^2 <= 4 on 32x32 grid),
// self sim fixed at -0.0005, others = (q_i . k_j)/sqrt(D) with k = normalized levels.
// Two kernels: (1) per-row scale = rsqrt(|v|^2) * log2(e)/sqrt(D), (2) local attention
// with 8 lanes/token, packed FFMA2, double-buffered neighbor pipeline, one EX2 per weight.

#define B_DIM 8
#define N_TOK 1024
#define L_DIM 6
#define D_DIM 128
#define ROWS (B_DIM * N_TOK * L_DIM)   // 49152
#define ROW_STRIDE (L_DIM * D_DIM)     // 768 floats between consecutive j
#define ROW_U2 (ROW_STRIDE / 4)        // 192 ulonglong2 per row

// sim->exp2 scale: (1/sqrt(128)) * log2(e)
#define C_SC 0.12751742119567576f

__device__ float g_scale[ROWS];   // rsqrt(|row|^2) * C_SC

// ---- packed f32x2 helpers (Blackwell FFMA2 path, PTX-only) ----
__device__ __forceinline__ unsigned long long pk2(float lo, float hi) {
    unsigned long long r;
    asm("mov.b64 %0, {%1, %2};" : "=l"(r) : "f"(lo), "f"(hi));
    return r;
}
__device__ __forceinline__ unsigned long long pk_fma(unsigned long long a,
                                                     unsigned long long b,
                                                     unsigned long long c) {
    unsigned long long d;
    asm("fma.rn.f32x2 %0, %1, %2, %3;" : "=l"(d) : "l"(a), "l"(b), "l"(c));
    return d;
}
__device__ __forceinline__ unsigned long long pk_mul(unsigned long long a,
                                                     unsigned long long b) {
    unsigned long long d;
    asm("mul.rn.f32x2 %0, %1, %2;" : "=l"(d) : "l"(a), "l"(b));
    return d;
}
__device__ __forceinline__ float pk_hadd(unsigned long long a) {
    float lo, hi;
    asm("mov.b64 {%0, %1}, %2;" : "=f"(lo), "=f"(hi) : "l"(a));
    return lo + hi;
}
__device__ __forceinline__ float rsqrt_approx(float x) {
    float r;
    asm("rsqrt.approx.f32 %0, %1;" : "=f"(r) : "f"(x));
    return r;
}
__device__ __forceinline__ float ex2_approx(float x) {
    float r;
    asm("ex2.approx.f32 %0, %1;" : "=f"(r) : "f"(x));
    return r;
}

// Kernel 1: per-row softmax scale. One warp per (b, j, l) row.
__global__ __launch_bounds__(256) void norm_kernel(const float* __restrict__ in) {
    int warp = (blockIdx.x * 256 + threadIdx.x) >> 5;
    int lane = threadIdx.x & 31;
    float4 v = ((const float4*)(in + (size_t)warp * D_DIM))[lane];
    float s = v.x * v.x + v.y * v.y + v.z * v.z + v.w * v.w;
    #pragma unroll
    for (int m = 16; m; m >>= 1) s += __shfl_xor_sync(0xffffffffu, s, m);
    if (lane == 0) g_scale[warp] = rsqrt_approx(fmaxf(s, 1e-24f)) * C_SC;
}

// Kernel 2: local attention. 8 lanes/token, 4 tokens/warp; lane owns floats
// {k*32 + lane*4 .. +3 : k=0..3} (fixed permutation, store uses same pattern).
// One neighbor per pipeline step, double-buffered; per-neighbor scale loaded in
// the prefetch stage so only the dp reduction sits on the critical path.
__global__ __launch_bounds__(256, 3) void attn_kernel(const float* __restrict__ in,
                                                      float* __restrict__ out) {
    const int tid  = threadIdx.x;
    const int gid  = (blockIdx.x * 256 + tid) >> 3;  // token id, 0..49151
    const int lane = tid & 7;

    const int i  = gid & (N_TOK - 1);
    const int bl = gid >> 10;          // b * L + l
    const int b  = bl / L_DIM;
    const int l  = bl - b * L_DIM;
    const int y  = i >> 5;
    const int x  = i & 31;

    // self row pointer; neighbor j = i + doff is at qr + doff*ROW_U2
    const ulonglong2* qr =
        (const ulonglong2*)(in + ((size_t)b * N_TOK * L_DIM + l) * D_DIM
                               + (size_t)i * ROW_STRIDE);
    const float* scp = g_scale + ((size_t)(b * N_TOK + i) * L_DIM + l);  // + doff*L_DIM

    ulonglong2 q[4];
    #pragma unroll
    for (int k = 0; k < 4; k++) q[k] = qr[k * 8 + lane];

    // Self term: sim = -0.0005 exactly; value = q.
    const float wself = 0.9995001249791693f;   // exp(-0.0005)
    float ssum = wself;
    const unsigned long long ws2 = pk2(wself, wself);
    unsigned long long acc[8];
    #pragma unroll
    for (int k = 0; k < 4; k++) {
        acc[2 * k]     = pk_mul(ws2, q[k].x);
        acc[2 * k + 1] = pk_mul(ws2, q[k].y);
    }

    // 12 non-self neighbors with dy^2 + dx^2 <= 4
    const int dys[12] = {-2, -1, -1, -1,  0,  0, 0, 0, 1, 1, 1, 2};
    const int dxs[12] = { 0, -1,  0,  1, -2, -1, 1, 2,-1, 0, 1, 0};

    ulonglong2 vb[2][4];   // [parity][d-chunk]
    float      sc[2];      // dp scale (0 if OOB)
    float      bi[2];      // exp2 bias: 0, or -100 if OOB (ex2 -> ~0)

    // Prologue: load neighbor 0
    {
        const int doff = dys[0] * 32 + dxs[0];
        bool ok = ((unsigned)(y + dys[0]) < 32u) & ((unsigned)(x + dxs[0]) < 32u);
        const int po = ok ? doff * ROW_U2 : 0;
        sc[0] = ok ? scp[doff * L_DIM] : 0.0f;
        bi[0] = ok ? 0.0f : -100.0f;
        #pragma unroll
        for (int k = 0; k < 4; k++) vb[0][k] = qr[po + k * 8 + lane];
    }

    #pragma unroll
    for (int t = 0; t < 12; t++) {
        const int cur = t & 1, nxt = cur ^ 1;

        // Prefetch next neighbor + its scale (off the critical path)
        if (t < 11) {
            const int doff = dys[t + 1] * 32 + dxs[t + 1];   // compile-time constant
            bool ok = ((unsigned)(y + dys[t + 1]) < 32u) & ((unsigned)(x + dxs[t + 1]) < 32u);
            const int po = ok ? doff * ROW_U2 : 0;
            sc[nxt] = ok ? scp[doff * L_DIM] : 0.0f;
            bi[nxt] = ok ? 0.0f : -100.0f;
            #pragma unroll
            for (int k = 0; k < 4; k++) vb[nxt][k] = qr[po + k * 8 + lane];
        }

        // Packed partial dot product q.v (8 FFMA2), then horizontal add
        unsigned long long d2 = pk_mul(q[0].x, vb[cur][0].x);
        d2 = pk_fma(q[0].y, vb[cur][0].y, d2);
        #pragma unroll
        for (int k = 1; k < 4; k++) {
            d2 = pk_fma(q[k].x, vb[cur][k].x, d2);
            d2 = pk_fma(q[k].y, vb[cur][k].y, d2);
        }
        float dp = pk_hadd(d2);

        // 8-lane butterfly reduce (each SHFL serves all 4 tokens in the warp)
        dp += __shfl_xor_sync(0xffffffffu, dp, 1);
        dp += __shfl_xor_sync(0xffffffffu, dp, 2);
        dp += __shfl_xor_sync(0xffffffffu, dp, 4);

        // w = 2^( dp * sc + bias );  OOB: sc=0, bias=-100 -> w ~ 0
        float w = ex2_approx(fmaf(dp, sc[cur], bi[cur]));
        ssum += w;
        const unsigned long long w2 = pk2(w, w);
        #pragma unroll
        for (int k = 0; k < 4; k++) {
            acc[2 * k]     = pk_fma(w2, vb[cur][k].x, acc[2 * k]);
            acc[2 * k + 1] = pk_fma(w2, vb[cur][k].y, acc[2 * k + 1]);
        }
    }

    const float inv = 1.0f / ssum;
    const unsigned long long inv2 = pk2(inv, inv);
    ulonglong2* orow = (ulonglong2*)(out + ((size_t)(b * N_TOK + i) * L_DIM + l) * D_DIM);
    #pragma unroll
    for (int k = 0; k < 4; k++) {
        ulonglong2 o;
        o.x = pk_mul(acc[2 * k], inv2);
        o.y = pk_mul(acc[2 * k + 1], inv2);
        orow[k * 8 + lane] = o;
    }
}

extern "C" void kernel_launch(void* const* d_in, const int* in_sizes, int n_in,
                              void* d_out, int out_size) {
    const float* in = (const float*)d_in[0];
    float* out = (float*)d_out;
    norm_kernel<<<ROWS / 8, 256>>>(in);          // 6144 blocks, 8 warps each
    attn_kernel<<<ROWS / 32, 256>>>(in, out);    // 1536 blocks, 32 tokens each
}

// round 9
// speedup vs baseline: 1.0713x; 1.0713x over previous
#include <cuda_runtime.h>

// ConsensusAttention: levels [B=8, N=1024, L=6, D=128] fp32.
// Local attention: each token attends to <=13 neighbors (dy^2+dx^2 <= 4 on 32x32 grid),
// self sim fixed at -0.0005, others = (q_i . k_j)/sqrt(D) with k = normalized levels.
// Kernel 1: per-row scale = rsqrt(|v|^2) * log2(e)/sqrt(D)  (8 lanes/row).
// Kernel 2: local attention, 16 lanes/token (2 tokens/warp), packed FFMA2,
// double-buffered neighbor pipeline, one EX2 per weight, 64-reg budget -> 4 blocks/SM.

#define B_DIM 8
#define N_TOK 1024
#define L_DIM 6
#define D_DIM 128
#define ROWS (B_DIM * N_TOK * L_DIM)   // 49152
#define ROW_STRIDE (L_DIM * D_DIM)     // 768 floats between consecutive j
#define ROW_U2 (ROW_STRIDE / 4)        // 192 ulonglong2 per row

// sim->exp2 scale: (1/sqrt(128)) * log2(e)
#define C_SC 0.12751742119567576f

__device__ float g_scale[ROWS];   // rsqrt(|row|^2) * C_SC

// ---- packed f32x2 helpers (Blackwell FFMA2 path, PTX-only) ----
__device__ __forceinline__ unsigned long long pk2(float lo, float hi) {
    unsigned long long r;
    asm("mov.b64 %0, {%1, %2};" : "=l"(r) : "f"(lo), "f"(hi));
    return r;
}
__device__ __forceinline__ unsigned long long pk_fma(unsigned long long a,
                                                     unsigned long long b,
                                                     unsigned long long c) {
    unsigned long long d;
    asm("fma.rn.f32x2 %0, %1, %2, %3;" : "=l"(d) : "l"(a), "l"(b), "l"(c));
    return d;
}
__device__ __forceinline__ unsigned long long pk_mul(unsigned long long a,
                                                     unsigned long long b) {
    unsigned long long d;
    asm("mul.rn.f32x2 %0, %1, %2;" : "=l"(d) : "l"(a), "l"(b));
    return d;
}
__device__ __forceinline__ float pk_hadd(unsigned long long a) {
    float lo, hi;
    asm("mov.b64 {%0, %1}, %2;" : "=f"(lo), "=f"(hi) : "l"(a));
    return lo + hi;
}
__device__ __forceinline__ float rsqrt_approx(float x) {
    float r;
    asm("rsqrt.approx.f32 %0, %1;" : "=f"(r) : "f"(x));
    return r;
}
__device__ __forceinline__ float ex2_approx(float x) {
    float r;
    asm("ex2.approx.f32 %0, %1;" : "=f"(r) : "f"(x));
    return r;
}

// Kernel 1: per-row softmax scale. 8 lanes per row, 4 rows per warp.
__global__ __launch_bounds__(256) void norm_kernel(const float* __restrict__ in) {
    int row  = (blockIdx.x * 256 + threadIdx.x) >> 3;
    int lane = threadIdx.x & 7;
    const float4* p = (const float4*)(in + (size_t)row * D_DIM);
    float4 v0 = p[lane], v1 = p[8 + lane], v2 = p[16 + lane], v3 = p[24 + lane];
    float s = v0.x * v0.x + v0.y * v0.y + v0.z * v0.z + v0.w * v0.w
            + v1.x * v1.x + v1.y * v1.y + v1.z * v1.z + v1.w * v1.w
            + v2.x * v2.x + v2.y * v2.y + v2.z * v2.z + v2.w * v2.w
            + v3.x * v3.x + v3.y * v3.y + v3.z * v3.z + v3.w * v3.w;
    s += __shfl_xor_sync(0xffffffffu, s, 1);
    s += __shfl_xor_sync(0xffffffffu, s, 2);
    s += __shfl_xor_sync(0xffffffffu, s, 4);
    if (lane == 0) g_scale[row] = rsqrt_approx(fmaxf(s, 1e-24f)) * C_SC;
}

// Kernel 2: local attention. 16 lanes/token (2 tokens/warp); lane owns 8 of
// 128 d-elements as 2 ulonglong2 (= 4 packed f32x2). One neighbor per pipeline
// step, double-buffered; per-neighbor scale loaded in the prefetch stage.
__global__ __launch_bounds__(256, 4) void attn_kernel(const float* __restrict__ in,
                                                      float* __restrict__ out) {
    const int tid  = threadIdx.x;
    const int gid  = (blockIdx.x * 256 + tid) >> 4;  // token id, 0..49151
    const int lane = tid & 15;

    const int i  = gid & (N_TOK - 1);
    const int bl = gid >> 10;          // b * L + l
    const int b  = bl / L_DIM;
    const int l  = bl - b * L_DIM;
    const int y  = i >> 5;
    const int x  = i & 31;

    // self row pointer; neighbor j = i + doff is at qr + doff*ROW_U2
    const ulonglong2* qr =
        (const ulonglong2*)(in + ((size_t)b * N_TOK * L_DIM + l) * D_DIM
                               + (size_t)i * ROW_STRIDE);
    const float* scp = g_scale + ((size_t)(b * N_TOK + i) * L_DIM + l);  // + doff*L_DIM

    const ulonglong2 q0 = qr[lane], q1 = qr[16 + lane];

    // Self term: sim = -0.0005 exactly; value = q.
    const float wself = 0.9995001249791693f;   // exp(-0.0005)
    float ssum = wself;
    const unsigned long long ws2 = pk2(wself, wself);
    unsigned long long a00 = pk_mul(ws2, q0.x);
    unsigned long long a01 = pk_mul(ws2, q0.y);
    unsigned long long a10 = pk_mul(ws2, q1.x);
    unsigned long long a11 = pk_mul(ws2, q1.y);

    // 12 non-self neighbors with dy^2 + dx^2 <= 4
    const int dys[12] = {-2, -1, -1, -1,  0,  0, 0, 0, 1, 1, 1, 2};
    const int dxs[12] = { 0, -1,  0,  1, -2, -1, 1, 2,-1, 0, 1, 0};

    ulonglong2 vb[2][2];   // [parity][d-chunk]
    float      sc[2];      // dp scale (0 if OOB)
    float      bi[2];      // exp2 bias: 0, or -100 if OOB (ex2 -> ~0)

    // Prologue: load neighbor 0
    {
        const int doff = dys[0] * 32 + dxs[0];
        bool ok = ((unsigned)(y + dys[0]) < 32u) & ((unsigned)(x + dxs[0]) < 32u);
        const int po = ok ? doff * ROW_U2 : 0;
        sc[0] = ok ? scp[doff * L_DIM] : 0.0f;
        bi[0] = ok ? 0.0f : -100.0f;
        vb[0][0] = qr[po + lane];
        vb[0][1] = qr[po + 16 + lane];
    }

    #pragma unroll
    for (int t = 0; t < 12; t++) {
        const int cur = t & 1, nxt = cur ^ 1;

        // Prefetch next neighbor + its scale (off the critical path)
        if (t < 11) {
            const int doff = dys[t + 1] * 32 + dxs[t + 1];   // compile-time constant
            bool ok = ((unsigned)(y + dys[t + 1]) < 32u) & ((unsigned)(x + dxs[t + 1]) < 32u);
            const int po = ok ? doff * ROW_U2 : 0;
            sc[nxt] = ok ? scp[doff * L_DIM] : 0.0f;
            bi[nxt] = ok ? 0.0f : -100.0f;
            vb[nxt][0] = qr[po + lane];
            vb[nxt][1] = qr[po + 16 + lane];
        }

        // Packed partial dot product q.v (4 FFMA2), then horizontal add
        unsigned long long d2 = pk_mul(q0.x, vb[cur][0].x);
        d2 = pk_fma(q0.y, vb[cur][0].y, d2);
        d2 = pk_fma(q1.x, vb[cur][1].x, d2);
        d2 = pk_fma(q1.y, vb[cur][1].y, d2);
        float dp = pk_hadd(d2);

        // 16-lane butterfly reduce (each SHFL serves both tokens in the warp)
        dp += __shfl_xor_sync(0xffffffffu, dp, 1);
        dp += __shfl_xor_sync(0xffffffffu, dp, 2);
        dp += __shfl_xor_sync(0xffffffffu, dp, 4);
        dp += __shfl_xor_sync(0xffffffffu, dp, 8);

        // w = 2^( dp * sc + bias );  OOB: sc=0, bias=-100 -> w ~ 0
        float w = ex2_approx(fmaf(dp, sc[cur], bi[cur]));
        ssum += w;
        const unsigned long long w2 = pk2(w, w);
        a00 = pk_fma(w2, vb[cur][0].x, a00);
        a01 = pk_fma(w2, vb[cur][0].y, a01);
        a10 = pk_fma(w2, vb[cur][1].x, a10);
        a11 = pk_fma(w2, vb[cur][1].y, a11);
    }

    const float inv = 1.0f / ssum;
    const unsigned long long inv2 = pk2(inv, inv);
    ulonglong2 o0, o1;
    o0.x = pk_mul(a00, inv2);
    o0.y = pk_mul(a01, inv2);
    o1.x = pk_mul(a10, inv2);
    o1.y = pk_mul(a11, inv2);

    ulonglong2* orow = (ulonglong2*)(out + ((size_t)(b * N_TOK + i) * L_DIM + l) * D_DIM);
    orow[lane] = o0;
    orow[16 + lane] = o1;
}

extern "C" void kernel_launch(void* const* d_in, const int* in_sizes, int n_in,
                              void* d_out, int out_size) {
    const float* in = (const float*)d_in[0];
    float* out = (float*)d_out;
    norm_kernel<<<ROWS / 32, 256>>>(in);         // 1536 blocks, 4 rows per warp
    attn_kernel<<<ROWS / 16, 256>>>(in, out);    // 3072 blocks, 16 tokens each
}